// round 16
// baseline (speedup 1.0000x reference)
#include <cuda_runtime.h>
#include <math.h>

// Problem constants
#define D_MODEL 768
#define NHEADS  12
#define NP      79         // stream nodes in resid_pre
#define SEQ     1024
#define NB      2
#define BS      2048       // NB*SEQ
#define DH      64
#define DMLP    3072
#define NNODE   92         // NP + NHEADS + 1

// ---------------- scratch (device globals; no allocations allowed) ----------------
__device__ float g_masked[BS * NHEADS * D_MODEL];   // masked resid per head, then LN1'd in place
__device__ float g_mlppart[BS * D_MODEL];           // partial mlp-mask sum over first NP nodes
__device__ float g_q[NB * NHEADS * SEQ * DH];
__device__ float g_k[NB * NHEADS * SEQ * DH];
__device__ float g_v[NB * NHEADS * SEQ * DH];
__device__ float g_z[NB * NHEADS * SEQ * DH];
__device__ float g_x2[BS * D_MODEL];
__device__ float g_hid[BS * DMLP];

// ---------------- kernel 1: fused edge-mask einsums + copy resid_pre to output ----
// One thread per (bs, d). Reads resid_pre exactly once.
__global__ __launch_bounds__(256) void k_mask_copy(
    const float* __restrict__ resid, const float* __restrict__ mA,
    const float* __restrict__ mM, float* __restrict__ out)
{
    __shared__ float sA[NP * NHEADS];
    __shared__ float sM[NP];
    int tid = threadIdx.x;
    for (int i = tid; i < NP * NHEADS; i += 256) sA[i] = mA[i];
    if (tid < NP) sM[tid] = mM[tid];
    __syncthreads();

    int idx = blockIdx.x * 256 + tid;       // 0 .. BS*D_MODEL-1
    int bs = idx / D_MODEL;
    int d  = idx % D_MODEL;
    const float* rp = resid + (bs * NP) * D_MODEL + d;
    float*       op = out   + (bs * NNODE) * D_MODEL + d;

    float acc[NHEADS];
#pragma unroll
    for (int h = 0; h < NHEADS; h++) acc[h] = 0.f;
    float ml = 0.f;

    for (int n = 0; n < NP; n++) {
        float r = rp[n * D_MODEL];
        op[n * D_MODEL] = r;                       // copy node to output
        ml = fmaf(r, sM[n], ml);
#pragma unroll
        for (int h = 0; h < NHEADS; h++) acc[h] = fmaf(r, sA[n * NHEADS + h], acc[h]);
    }
#pragma unroll
    for (int h = 0; h < NHEADS; h++)
        g_masked[(bs * NHEADS + h) * D_MODEL + d] = acc[h];
    g_mlppart[bs * D_MODEL + d] = ml;
}

// ---------------- LN1 (in place on g_masked), one block per (bs,h) row ------------
__global__ __launch_bounds__(256) void k_ln1(const float* __restrict__ w, const float* __restrict__ b)
{
    int row = blockIdx.x;                       // BS*NHEADS rows
    float* x = g_masked + row * D_MODEL;
    int tid = threadIdx.x;
    float v0 = x[tid], v1 = x[tid + 256], v2 = x[tid + 512];
    float s = v0 + v1 + v2;
    float q = v0 * v0 + v1 * v1 + v2 * v2;
    __shared__ float ws[8], wq[8], stat[2];
#pragma unroll
    for (int o = 16; o > 0; o >>= 1) {
        s += __shfl_xor_sync(0xffffffffu, s, o);
        q += __shfl_xor_sync(0xffffffffu, q, o);
    }
    if ((tid & 31) == 0) { ws[tid >> 5] = s; wq[tid >> 5] = q; }
    __syncthreads();
    if (tid == 0) {
        float ts = 0.f, tq = 0.f;
#pragma unroll
        for (int i = 0; i < 8; i++) { ts += ws[i]; tq += wq[i]; }
        float mu  = ts * (1.f / 768.f);
        float var = tq * (1.f / 768.f) - mu * mu;
        stat[0] = mu; stat[1] = 1.f / sqrtf(var + 1e-5f);
    }
    __syncthreads();
    float mu = stat[0], inv = stat[1];
    x[tid]       = (v0 - mu) * inv * w[tid]       + b[tid];
    x[tid + 256] = (v1 - mu) * inv * w[tid + 256] + b[tid + 256];
    x[tid + 512] = (v2 - mu) * inv * w[tid + 512] + b[tid + 512];
}

// ---------------- LN2: head-sum + layernorm, one block per bs ----------------------
__global__ __launch_bounds__(256) void k_ln2(
    const float* __restrict__ mM, const float* __restrict__ w,
    const float* __restrict__ b, const float* __restrict__ out)
{
    int bs = blockIdx.x;
    int tid = threadIdx.x;
    __shared__ float sm[NHEADS];
    __shared__ float ws[8], wq[8], stat[2];
    if (tid < NHEADS) sm[tid] = mM[NP + tid];
    __syncthreads();

    float v[3];
    float s = 0.f, q = 0.f;
#pragma unroll
    for (int j = 0; j < 3; j++) {
        int d = tid + j * 256;
        float val = g_mlppart[bs * D_MODEL + d];
        const float* op = out + (bs * NNODE + NP) * D_MODEL + d;
#pragma unroll
        for (int hh = 0; hh < NHEADS; hh++) val = fmaf(sm[hh], op[hh * D_MODEL], val);
        v[j] = val;
        s += val; q += val * val;
    }
#pragma unroll
    for (int o = 16; o > 0; o >>= 1) {
        s += __shfl_xor_sync(0xffffffffu, s, o);
        q += __shfl_xor_sync(0xffffffffu, q, o);
    }
    if ((tid & 31) == 0) { ws[tid >> 5] = s; wq[tid >> 5] = q; }
    __syncthreads();
    if (tid == 0) {
        float ts = 0.f, tq = 0.f;
#pragma unroll
        for (int i = 0; i < 8; i++) { ts += ws[i]; tq += wq[i]; }
        float mu  = ts * (1.f / 768.f);
        float var = tq * (1.f / 768.f) - mu * mu;
        stat[0] = mu; stat[1] = 1.f / sqrtf(var + 1e-5f);
    }
    __syncthreads();
    float mu = stat[0], inv = stat[1];
#pragma unroll
    for (int j = 0; j < 3; j++) {
        int d = tid + j * 256;
        g_x2[bs * D_MODEL + d] = (v[j] - mu) * inv * w[d] + b[d];
    }
}

// ---------------- GELU (GPT-2 tanh approximation) ---------------------------------
__device__ __forceinline__ float gelu_new(float x)
{
    float x3 = x * x * x;
    float t = tanhf(0.7978845608028654f * (x + 0.044715f * x3));
    return 0.5f * x * (1.f + t);
}

// ---------------- generic 64x64x32 fp32 tiled GEMM --------------------------------
// MODE 0: QKV   A=g_masked  -> g_q/g_k/g_v
// MODE 1: W_O   A=g_z       -> out node NP+h
// MODE 2: MLPin A=g_x2      -> g_hid (gelu)
// MODE 3: MLPout A=g_hid    -> out node 91
template<int MODE>
__global__ __launch_bounds__(256) void gemm64(
    const float* __restrict__ W0, const float* __restrict__ W1, const float* __restrict__ W2,
    const float* __restrict__ B0, const float* __restrict__ B1, const float* __restrict__ B2,
    float* __restrict__ out)
{
    constexpr int KD  = (MODE == 0) ? 768 : (MODE == 1) ? 64  : (MODE == 2) ? 768  : 3072;
    constexpr int LDB = (MODE == 0) ? 64  : (MODE == 1) ? 768 : (MODE == 2) ? 3072 : 768;

    __shared__ float As[32][65];   // transposed A tile, conflict-free store & broadcast read
    __shared__ float Bs[32][64];   // row-major B tile, float4 reads

    const int tid = threadIdx.x;
    const int m0 = blockIdx.x * 64;
    const int n0 = blockIdx.y * 64;
    int h = 0, mat = 0;
    const float* Bw = W0;
    const float* bv = B0;
    if (MODE == 0) {
        mat = blockIdx.z / NHEADS; h = blockIdx.z % NHEADS;
        Bw = (mat == 0 ? W0 : (mat == 1 ? W1 : W2)) + h * (768 * 64);
        bv = (mat == 0 ? B0 : (mat == 1 ? B1 : B2)) + h * 64;
    }
    if (MODE == 1) { h = blockIdx.z; Bw = W0 + h * (64 * 768); }

    const int klane = tid & 31, mro = tid >> 5;   // A-load: lane = k, 8 rows / thread
    const int bkk = tid >> 6, bn = tid & 63;      // B-load

    float acc[4][4] = {};

    for (int k0 = 0; k0 < KD; k0 += 32) {
#pragma unroll
        for (int i = 0; i < 8; i++) {
            int m = m0 + mro + i * 8;
            const float* ap;
            if (MODE == 0)      ap = g_masked + m * (NHEADS * D_MODEL) + h * D_MODEL;
            else if (MODE == 1) { int bb = m >> 10, ss = m & 1023; ap = g_z + ((bb * NHEADS + h) * SEQ + ss) * DH; }
            else if (MODE == 2) ap = g_x2 + m * D_MODEL;
            else                ap = g_hid + m * DMLP;
            As[klane][mro + i * 8] = ap[k0 + klane];
        }
#pragma unroll
        for (int i = 0; i < 8; i++) {
            int kk = bkk + i * 4;
            Bs[kk][bn] = Bw[(k0 + kk) * LDB + n0 + bn];
        }
        __syncthreads();

        const int ty4 = (tid >> 4) << 2, tx4 = (tid & 15) << 2;
#pragma unroll
        for (int kk = 0; kk < 32; kk++) {
            float4 b4 = *(const float4*)&Bs[kk][tx4];
            float a0 = As[kk][ty4], a1 = As[kk][ty4 + 1], a2 = As[kk][ty4 + 2], a3 = As[kk][ty4 + 3];
            acc[0][0] = fmaf(a0, b4.x, acc[0][0]); acc[0][1] = fmaf(a0, b4.y, acc[0][1]);
            acc[0][2] = fmaf(a0, b4.z, acc[0][2]); acc[0][3] = fmaf(a0, b4.w, acc[0][3]);
            acc[1][0] = fmaf(a1, b4.x, acc[1][0]); acc[1][1] = fmaf(a1, b4.y, acc[1][1]);
            acc[1][2] = fmaf(a1, b4.z, acc[1][2]); acc[1][3] = fmaf(a1, b4.w, acc[1][3]);
            acc[2][0] = fmaf(a2, b4.x, acc[2][0]); acc[2][1] = fmaf(a2, b4.y, acc[2][1]);
            acc[2][2] = fmaf(a2, b4.z, acc[2][2]); acc[2][3] = fmaf(a2, b4.w, acc[2][3]);
            acc[3][0] = fmaf(a3, b4.x, acc[3][0]); acc[3][1] = fmaf(a3, b4.y, acc[3][1]);
            acc[3][2] = fmaf(a3, b4.z, acc[3][2]); acc[3][3] = fmaf(a3, b4.w, acc[3][3]);
        }
        __syncthreads();
    }

    // epilogue
    const int ty4 = (tid >> 4) << 2, tx4 = (tid & 15) << 2;
#pragma unroll
    for (int i = 0; i < 4; i++) {
        int m = m0 + ty4 + i;
        float4 r;
        if (MODE == 0) {
            r.x = acc[i][0] + bv[tx4 + 0]; r.y = acc[i][1] + bv[tx4 + 1];
            r.z = acc[i][2] + bv[tx4 + 2]; r.w = acc[i][3] + bv[tx4 + 3];
            int bb = m >> 10, ss = m & 1023;
            float* dst = (mat == 0 ? g_q : (mat == 1 ? g_k : g_v));
            *(float4*)&dst[((bb * NHEADS + h) * SEQ + ss) * DH + tx4] = r;
        } else if (MODE == 1) {
            const float inv_h = 1.f / (float)NHEADS;
            r.x = acc[i][0] + B0[n0 + tx4 + 0] * inv_h; r.y = acc[i][1] + B0[n0 + tx4 + 1] * inv_h;
            r.z = acc[i][2] + B0[n0 + tx4 + 2] * inv_h; r.w = acc[i][3] + B0[n0 + tx4 + 3] * inv_h;
            *(float4*)&out[(m * NNODE + NP + h) * D_MODEL + n0 + tx4] = r;
        } else if (MODE == 2) {
            r.x = gelu_new(acc[i][0] + B0[n0 + tx4 + 0]); r.y = gelu_new(acc[i][1] + B0[n0 + tx4 + 1]);
            r.z = gelu_new(acc[i][2] + B0[n0 + tx4 + 2]); r.w = gelu_new(acc[i][3] + B0[n0 + tx4 + 3]);
            *(float4*)&g_hid[m * DMLP + n0 + tx4] = r;
        } else {
            r.x = acc[i][0] + B0[n0 + tx4 + 0]; r.y = acc[i][1] + B0[n0 + tx4 + 1];
            r.z = acc[i][2] + B0[n0 + tx4 + 2]; r.w = acc[i][3] + B0[n0 + tx4 + 3];
            *(float4*)&out[(m * NNODE + (NNODE - 1)) * D_MODEL + n0 + tx4] = r;
        }
    }
}

// ---------------- flash-attention style causal attention ---------------------------
// Block = (b, h, 64-query tile). 256 threads in a 16x16 grid; each thread owns a
// 4x4 fragment of the 64x64 score tile and a 4x4 fragment of the 64x64 O tile.
// K-tiles of 64 keys; online softmax carried in registers.
#define ATTN_SMEM (4 * 64 * 68 * 4)

__global__ __launch_bounds__(256) void k_attn()
{
    extern __shared__ float smem[];
    float (*Qt)[68] = (float(*)[68])(smem);                 // [d][query], pre-scaled
    float (*Kt)[68] = (float(*)[68])(smem + 64 * 68);       // [d][key]
    float (*Vs)[68] = (float(*)[68])(smem + 2 * 64 * 68);   // [key][d]
    float (*Ps)[68] = (float(*)[68])(smem + 3 * 64 * 68);   // [query][key]

    const int qt = blockIdx.x, h = blockIdx.y, b = blockIdx.z;
    const int bh = b * NHEADS + h;
    const int q0 = qt * 64;
    const float* __restrict__ Qb = g_q + (size_t)bh * SEQ * DH;
    const float* __restrict__ Kb = g_k + (size_t)bh * SEQ * DH;
    const float* __restrict__ Vb = g_v + (size_t)bh * SEQ * DH;

    const int tid = threadIdx.x;
    const int ty = tid >> 4, tx = tid & 15;
    const int r0 = ty << 2, c0 = tx << 2;

    // load Q tile transposed into smem, folding the 1/sqrt(64) scale
    {
        int q = tid >> 2, d0 = (tid & 3) << 4;
        const float* src = Qb + (q0 + q) * DH + d0;
#pragma unroll
        for (int j = 0; j < 16; j += 4) {
            float4 v = *(const float4*)(src + j);
            Qt[d0 + j + 0][q] = v.x * 0.125f;
            Qt[d0 + j + 1][q] = v.y * 0.125f;
            Qt[d0 + j + 2][q] = v.z * 0.125f;
            Qt[d0 + j + 3][q] = v.w * 0.125f;
        }
    }

    float m_i[4], l_i[4], o[4][4];
#pragma unroll
    for (int i = 0; i < 4; i++) {
        m_i[i] = -1e30f; l_i[i] = 0.f;
#pragma unroll
        for (int j = 0; j < 4; j++) o[i][j] = 0.f;
    }

    for (int kt = 0; kt <= qt; kt++) {
        const int k0 = kt * 64;
        // load K tile (transposed) and V tile
        {
            int kk = tid >> 2, d0 = (tid & 3) << 4;
            const float* ksrc = Kb + (k0 + kk) * DH + d0;
            const float* vsrc = Vb + (k0 + kk) * DH + d0;
#pragma unroll
            for (int j = 0; j < 16; j += 4) {
                float4 kv = *(const float4*)(ksrc + j);
                Kt[d0 + j + 0][kk] = kv.x;
                Kt[d0 + j + 1][kk] = kv.y;
                Kt[d0 + j + 2][kk] = kv.z;
                Kt[d0 + j + 3][kk] = kv.w;
                *(float4*)&Vs[kk][d0 + j] = *(const float4*)(vsrc + j);
            }
        }
        __syncthreads();

        // S tile: s[i][j] = sum_d Q[r0+i][d] * K[c0+j][d]  (already scaled)
        float s[4][4] = {};
#pragma unroll
        for (int d = 0; d < 64; d++) {
            float4 a4 = *(const float4*)&Qt[d][r0];
            float4 b4 = *(const float4*)&Kt[d][c0];
            s[0][0] = fmaf(a4.x, b4.x, s[0][0]); s[0][1] = fmaf(a4.x, b4.y, s[0][1]);
            s[0][2] = fmaf(a4.x, b4.z, s[0][2]); s[0][3] = fmaf(a4.x, b4.w, s[0][3]);
            s[1][0] = fmaf(a4.y, b4.x, s[1][0]); s[1][1] = fmaf(a4.y, b4.y, s[1][1]);
            s[1][2] = fmaf(a4.y, b4.z, s[1][2]); s[1][3] = fmaf(a4.y, b4.w, s[1][3]);
            s[2][0] = fmaf(a4.z, b4.x, s[2][0]); s[2][1] = fmaf(a4.z, b4.y, s[2][1]);
            s[2][2] = fmaf(a4.z, b4.z, s[2][2]); s[2][3] = fmaf(a4.z, b4.w, s[2][3]);
            s[3][0] = fmaf(a4.w, b4.x, s[3][0]); s[3][1] = fmaf(a4.w, b4.y, s[3][1]);
            s[3][2] = fmaf(a4.w, b4.z, s[3][2]); s[3][3] = fmaf(a4.w, b4.w, s[3][3]);
        }

        // causal mask (only the diagonal tile mixes valid/invalid)
        if (kt == qt) {
#pragma unroll
            for (int i = 0; i < 4; i++)
#pragma unroll
                for (int j = 0; j < 4; j++)
                    if (c0 + j > r0 + i) s[i][j] = -1e30f;
        }

        // online softmax per row; reductions across the 16 tx lanes
#pragma unroll
        for (int i = 0; i < 4; i++) {
            float mi = fmaxf(fmaxf(s[i][0], s[i][1]), fmaxf(s[i][2], s[i][3]));
#pragma unroll
            for (int off = 1; off < 16; off <<= 1)
                mi = fmaxf(mi, __shfl_xor_sync(0xffffffffu, mi, off));
            float mnew = fmaxf(m_i[i], mi);
            float corr = __expf(m_i[i] - mnew);
            m_i[i] = mnew;
            float p0 = __expf(s[i][0] - mnew);
            float p1 = __expf(s[i][1] - mnew);
            float p2 = __expf(s[i][2] - mnew);
            float p3 = __expf(s[i][3] - mnew);
            float rs = (p0 + p1) + (p2 + p3);
#pragma unroll
            for (int off = 1; off < 16; off <<= 1)
                rs += __shfl_xor_sync(0xffffffffu, rs, off);
            l_i[i] = l_i[i] * corr + rs;
            o[i][0] *= corr; o[i][1] *= corr; o[i][2] *= corr; o[i][3] *= corr;
            *(float4*)&Ps[r0 + i][c0] = make_float4(p0, p1, p2, p3);
        }
        __syncthreads();

        // O += P @ V
#pragma unroll
        for (int kk = 0; kk < 64; kk++) {
            float4 b4 = *(const float4*)&Vs[kk][c0];
            float a0 = Ps[r0 + 0][kk];
            float a1 = Ps[r0 + 1][kk];
            float a2 = Ps[r0 + 2][kk];
            float a3 = Ps[r0 + 3][kk];
            o[0][0] = fmaf(a0, b4.x, o[0][0]); o[0][1] = fmaf(a0, b4.y, o[0][1]);
            o[0][2] = fmaf(a0, b4.z, o[0][2]); o[0][3] = fmaf(a0, b4.w, o[0][3]);
            o[1][0] = fmaf(a1, b4.x, o[1][0]); o[1][1] = fmaf(a1, b4.y, o[1][1]);
            o[1][2] = fmaf(a1, b4.z, o[1][2]); o[1][3] = fmaf(a1, b4.w, o[1][3]);
            o[2][0] = fmaf(a2, b4.x, o[2][0]); o[2][1] = fmaf(a2, b4.y, o[2][1]);
            o[2][2] = fmaf(a2, b4.z, o[2][2]); o[2][3] = fmaf(a2, b4.w, o[2][3]);
            o[3][0] = fmaf(a3, b4.x, o[3][0]); o[3][1] = fmaf(a3, b4.y, o[3][1]);
            o[3][2] = fmaf(a3, b4.z, o[3][2]); o[3][3] = fmaf(a3, b4.w, o[3][3]);
        }
        __syncthreads();
    }

    // normalize and write z
#pragma unroll
    for (int i = 0; i < 4; i++) {
        float inv = 1.f / l_i[i];
        float4 r = make_float4(o[i][0] * inv, o[i][1] * inv, o[i][2] * inv, o[i][3] * inv);
        *(float4*)&g_z[((size_t)bh * SEQ + q0 + r0 + i) * DH + c0] = r;
    }
}

// ---------------- launch -----------------------------------------------------------
extern "C" void kernel_launch(void* const* d_in, const int* in_sizes, int n_in,
                              void* d_out, int out_size)
{
    const float* resid = (const float*)d_in[0];
    const float* mA    = (const float*)d_in[1];
    const float* mM    = (const float*)d_in[2];
    const float* ln1w  = (const float*)d_in[3];
    const float* ln1b  = (const float*)d_in[4];
    const float* ln2w  = (const float*)d_in[5];
    const float* ln2b  = (const float*)d_in[6];
    const float* WQ    = (const float*)d_in[7];
    const float* bQ    = (const float*)d_in[8];
    const float* WK    = (const float*)d_in[9];
    const float* bK    = (const float*)d_in[10];
    const float* WV    = (const float*)d_in[11];
    const float* bV    = (const float*)d_in[12];
    const float* WO    = (const float*)d_in[13];
    const float* bO    = (const float*)d_in[14];
    const float* Win   = (const float*)d_in[15];
    const float* bin   = (const float*)d_in[16];
    const float* Wout  = (const float*)d_in[17];
    const float* bout  = (const float*)d_in[18];
    float* out = (float*)d_out;

    static bool attr_set = false;
    if (!attr_set) {
        cudaFuncSetAttribute(k_attn, cudaFuncAttributeMaxDynamicSharedMemorySize, ATTN_SMEM);
        attr_set = true;
    }

    // 1) fused edge-mask einsums + resid copy
    k_mask_copy<<<(BS * D_MODEL) / 256, 256>>>(resid, mA, mM, out);
    // 2) LN1 (in place)
    k_ln1<<<BS * NHEADS, 256>>>(ln1w, ln1b);
    // 3) Q,K,V projections (36 batched 2048x768x64 GEMMs)
    gemm64<0><<<dim3(32, 1, 3 * NHEADS), 256>>>(WQ, WK, WV, bQ, bK, bV, nullptr);
    // 4) causal attention (flash-style, 64-query tiles)
    k_attn<<<dim3(SEQ / 64, NHEADS, NB), 256, ATTN_SMEM>>>();
    // 5) per-head output projection -> output nodes 79..90
    gemm64<1><<<dim3(32, 12, NHEADS), 256>>>(WO, nullptr, nullptr, bO, nullptr, nullptr, out);
    // 6) MLP residual mask-sum + LN2
    k_ln2<<<BS, 256>>>(mM, ln2w, ln2b, out);
    // 7) MLP in (gelu)
    gemm64<2><<<dim3(32, 48, 1), 256>>>(Win, nullptr, nullptr, bin, nullptr, nullptr, nullptr);
    // 8) MLP out -> output node 91
    gemm64<3><<<dim3(32, 12, 1), 256>>>(Wout, nullptr, nullptr, bout, nullptr, nullptr, out);
}

// round 17
// speedup vs baseline: 1.4961x; 1.4961x over previous
#include <cuda_runtime.h>
#include <math.h>
#include <stdint.h>

// Problem constants
#define D_MODEL 768
#define NHEADS  12
#define NP      79         // stream nodes in resid_pre
#define SEQ     1024
#define NB      2
#define BS      2048       // NB*SEQ
#define DH      64
#define DMLP    3072
#define NNODE   92         // NP + NHEADS + 1

// ---------------- scratch (device globals; no allocations allowed) ----------------
__device__ float g_masked[BS * NHEADS * D_MODEL];   // masked resid per head, then LN1'd in place
__device__ float g_mlppart[BS * D_MODEL];           // partial mlp-mask sum over first NP nodes
__device__ float g_q[NB * NHEADS * SEQ * DH];
__device__ float g_k[NB * NHEADS * SEQ * DH];
__device__ float g_v[NB * NHEADS * SEQ * DH];
__device__ float g_z[NB * NHEADS * SEQ * DH];
__device__ float g_x2[BS * D_MODEL];
__device__ float g_hid[BS * DMLP];

// ---------------- kernel 1: fused edge-mask einsums + copy resid_pre to output ----
__global__ __launch_bounds__(256) void k_mask_copy(
    const float* __restrict__ resid, const float* __restrict__ mA,
    const float* __restrict__ mM, float* __restrict__ out)
{
    __shared__ float sA[NP * NHEADS];
    __shared__ float sM[NP];
    int tid = threadIdx.x;
    for (int i = tid; i < NP * NHEADS; i += 256) sA[i] = mA[i];
    if (tid < NP) sM[tid] = mM[tid];
    __syncthreads();

    int idx = blockIdx.x * 256 + tid;       // 0 .. BS*D_MODEL-1
    int bs = idx / D_MODEL;
    int d  = idx % D_MODEL;
    const float* rp = resid + (bs * NP) * D_MODEL + d;
    float*       op = out   + (bs * NNODE) * D_MODEL + d;

    float acc[NHEADS];
#pragma unroll
    for (int h = 0; h < NHEADS; h++) acc[h] = 0.f;
    float ml = 0.f;

    for (int n = 0; n < NP; n++) {
        float r = rp[n * D_MODEL];
        op[n * D_MODEL] = r;                       // copy node to output
        ml = fmaf(r, sM[n], ml);
#pragma unroll
        for (int h = 0; h < NHEADS; h++) acc[h] = fmaf(r, sA[n * NHEADS + h], acc[h]);
    }
#pragma unroll
    for (int h = 0; h < NHEADS; h++)
        g_masked[(bs * NHEADS + h) * D_MODEL + d] = acc[h];
    g_mlppart[bs * D_MODEL + d] = ml;
}

// ---------------- LN1 (in place on g_masked), one block per (bs,h) row ------------
__global__ __launch_bounds__(256) void k_ln1(const float* __restrict__ w, const float* __restrict__ b)
{
    int row = blockIdx.x;                       // BS*NHEADS rows
    float* x = g_masked + row * D_MODEL;
    int tid = threadIdx.x;
    float v0 = x[tid], v1 = x[tid + 256], v2 = x[tid + 512];
    float s = v0 + v1 + v2;
    float q = v0 * v0 + v1 * v1 + v2 * v2;
    __shared__ float ws[8], wq[8], stat[2];
#pragma unroll
    for (int o = 16; o > 0; o >>= 1) {
        s += __shfl_xor_sync(0xffffffffu, s, o);
        q += __shfl_xor_sync(0xffffffffu, q, o);
    }
    if ((tid & 31) == 0) { ws[tid >> 5] = s; wq[tid >> 5] = q; }
    __syncthreads();
    if (tid == 0) {
        float ts = 0.f, tq = 0.f;
#pragma unroll
        for (int i = 0; i < 8; i++) { ts += ws[i]; tq += wq[i]; }
        float mu  = ts * (1.f / 768.f);
        float var = tq * (1.f / 768.f) - mu * mu;
        stat[0] = mu; stat[1] = 1.f / sqrtf(var + 1e-5f);
    }
    __syncthreads();
    float mu = stat[0], inv = stat[1];
    x[tid]       = (v0 - mu) * inv * w[tid]       + b[tid];
    x[tid + 256] = (v1 - mu) * inv * w[tid + 256] + b[tid + 256];
    x[tid + 512] = (v2 - mu) * inv * w[tid + 512] + b[tid + 512];
}

// ---------------- LN2: head-sum + layernorm, one block per bs ----------------------
__global__ __launch_bounds__(256) void k_ln2(
    const float* __restrict__ mM, const float* __restrict__ w,
    const float* __restrict__ b, const float* __restrict__ out)
{
    int bs = blockIdx.x;
    int tid = threadIdx.x;
    __shared__ float sm[NHEADS];
    __shared__ float ws[8], wq[8], stat[2];
    if (tid < NHEADS) sm[tid] = mM[NP + tid];
    __syncthreads();

    float v[3];
    float s = 0.f, q = 0.f;
#pragma unroll
    for (int j = 0; j < 3; j++) {
        int d = tid + j * 256;
        float val = g_mlppart[bs * D_MODEL + d];
        const float* op = out + (bs * NNODE + NP) * D_MODEL + d;
#pragma unroll
        for (int hh = 0; hh < NHEADS; hh++) val = fmaf(sm[hh], op[hh * D_MODEL], val);
        v[j] = val;
        s += val; q += val * val;
    }
#pragma unroll
    for (int o = 16; o > 0; o >>= 1) {
        s += __shfl_xor_sync(0xffffffffu, s, o);
        q += __shfl_xor_sync(0xffffffffu, q, o);
    }
    if ((tid & 31) == 0) { ws[tid >> 5] = s; wq[tid >> 5] = q; }
    __syncthreads();
    if (tid == 0) {
        float ts = 0.f, tq = 0.f;
#pragma unroll
        for (int i = 0; i < 8; i++) { ts += ws[i]; tq += wq[i]; }
        float mu  = ts * (1.f / 768.f);
        float var = tq * (1.f / 768.f) - mu * mu;
        stat[0] = mu; stat[1] = 1.f / sqrtf(var + 1e-5f);
    }
    __syncthreads();
    float mu = stat[0], inv = stat[1];
#pragma unroll
    for (int j = 0; j < 3; j++) {
        int d = tid + j * 256;
        g_x2[bs * D_MODEL + d] = (v[j] - mu) * inv * w[d] + b[d];
    }
}

// ---------------- GELU (GPT-2 tanh approximation) ---------------------------------
__device__ __forceinline__ float gelu_new(float x)
{
    float x3 = x * x * x;
    float t = tanhf(0.7978845608028654f * (x + 0.044715f * x3));
    return 0.5f * x * (1.f + t);
}

// ---------------- tf32 helpers -----------------------------------------------------
__device__ __forceinline__ float to_tf32(float x)
{
    uint32_t u;
    asm("cvt.rna.tf32.f32 %0, %1;" : "=r"(u) : "f"(x));
    return __uint_as_float(u);
}

__device__ __forceinline__ void mma_tf32(float* d, const float* a, const float* b)
{
    asm volatile(
        "mma.sync.aligned.m16n8k8.row.col.f32.tf32.tf32.f32 "
        "{%0,%1,%2,%3}, {%4,%5,%6,%7}, {%8,%9}, {%0,%1,%2,%3};\n"
        : "+f"(d[0]), "+f"(d[1]), "+f"(d[2]), "+f"(d[3])
        : "r"(__float_as_uint(a[0])), "r"(__float_as_uint(a[1])),
          "r"(__float_as_uint(a[2])), "r"(__float_as_uint(a[3])),
          "r"(__float_as_uint(b[0])), "r"(__float_as_uint(b[1])));
}

// ---------------- tensor-core tf32 GEMM, 128x64 block tile, BK=16 ------------------
// MODE 0: QKV    A=g_masked  -> g_q/g_k/g_v
// MODE 1: W_O    A=g_z       -> out node NP+h
// MODE 2: MLPin  A=g_x2      -> g_hid (gelu)
// MODE 3: MLPout A=g_hid     -> out node 91
// 8 warps in a 4x2 grid; each warp owns a 32x32 tile = 2(m16) x 4(n8) mma fragments.
template<int MODE>
__global__ __launch_bounds__(256) void gemm_tc(
    const float* __restrict__ W0, const float* __restrict__ W1, const float* __restrict__ W2,
    const float* __restrict__ B0, const float* __restrict__ B1, const float* __restrict__ B2,
    float* __restrict__ out)
{
    constexpr int KD  = (MODE == 0) ? 768 : (MODE == 1) ? 64  : (MODE == 2) ? 768  : 3072;
    constexpr int LDB = (MODE == 0) ? 64  : (MODE == 1) ? 768 : (MODE == 2) ? 3072 : 768;

    __shared__ float As[128][20];   // [m][k], stride 20 -> conflict-free fragment reads
    __shared__ float Bs[16][72];    // [k][n], stride 72 -> conflict-free fragment reads

    const int tid = threadIdx.x;
    const int m0 = blockIdx.x * 128;
    const int n0 = blockIdx.y * 64;
    int h = 0, mat = 0;
    const float* Bw = W0;
    const float* bv = B0;
    if (MODE == 0) {
        mat = blockIdx.z / NHEADS; h = blockIdx.z % NHEADS;
        Bw = (mat == 0 ? W0 : (mat == 1 ? W1 : W2)) + h * (768 * 64);
        bv = (mat == 0 ? B0 : (mat == 1 ? B1 : B2)) + h * 64;
    }
    if (MODE == 1) { h = blockIdx.z; Bw = W0 + h * (64 * 768); }

    const int lane = tid & 31, wid = tid >> 5;
    const int warp_m = (wid >> 1) * 32;   // 0,32,64,96
    const int warp_n = (wid & 1) * 32;    // 0,32
    const int gid = lane >> 2, tig = lane & 3;

    float acc[2][4][4];
#pragma unroll
    for (int i = 0; i < 2; i++)
#pragma unroll
        for (int j = 0; j < 4; j++)
#pragma unroll
            for (int c = 0; c < 4; c++) acc[i][j][c] = 0.f;

    for (int k0 = 0; k0 < KD; k0 += 16) {
        // ---- load A tile [128][16], converted to tf32 ----
#pragma unroll
        for (int rep = 0; rep < 2; rep++) {
            int idx = rep * 256 + tid;
            int row = idx >> 2, qo = (idx & 3) << 2;
            int m = m0 + row;
            const float* ap;
            if (MODE == 0)      ap = g_masked + m * (NHEADS * D_MODEL) + h * D_MODEL;
            else if (MODE == 1) { int bb = m >> 10, ss = m & 1023; ap = g_z + ((bb * NHEADS + h) * SEQ + ss) * DH; }
            else if (MODE == 2) ap = g_x2 + m * D_MODEL;
            else                ap = g_hid + m * DMLP;
            float4 v = *(const float4*)(ap + k0 + qo);
            v.x = to_tf32(v.x); v.y = to_tf32(v.y); v.z = to_tf32(v.z); v.w = to_tf32(v.w);
            *(float4*)&As[row][qo] = v;
        }
        // ---- load B tile [16][64], converted to tf32 ----
        {
            int row = tid >> 4, c4 = (tid & 15) << 2;
            float4 v = *(const float4*)(Bw + (k0 + row) * LDB + n0 + c4);
            v.x = to_tf32(v.x); v.y = to_tf32(v.y); v.z = to_tf32(v.z); v.w = to_tf32(v.w);
            *(float4*)&Bs[row][c4] = v;
        }
        __syncthreads();

        // ---- 2 k-steps of m16n8k8 ----
#pragma unroll
        for (int kc = 0; kc < 16; kc += 8) {
            float a[2][4];
#pragma unroll
            for (int i = 0; i < 2; i++) {
                a[i][0] = As[warp_m + i * 16 + gid    ][kc + tig];
                a[i][1] = As[warp_m + i * 16 + gid + 8][kc + tig];
                a[i][2] = As[warp_m + i * 16 + gid    ][kc + tig + 4];
                a[i][3] = As[warp_m + i * 16 + gid + 8][kc + tig + 4];
            }
            float b[4][2];
#pragma unroll
            for (int j = 0; j < 4; j++) {
                b[j][0] = Bs[kc + tig    ][warp_n + j * 8 + gid];
                b[j][1] = Bs[kc + tig + 4][warp_n + j * 8 + gid];
            }
#pragma unroll
            for (int i = 0; i < 2; i++)
#pragma unroll
                for (int j = 0; j < 4; j++)
                    mma_tf32(acc[i][j], a[i], b[j]);
        }
        __syncthreads();
    }

    // ---- epilogue ----
    const float inv_h = 1.f / (float)NHEADS;
#pragma unroll
    for (int i = 0; i < 2; i++) {
#pragma unroll
        for (int j = 0; j < 4; j++) {
            int nl = warp_n + j * 8 + 2 * tig;      // local n (0..63), even
            int n  = n0 + nl;
#pragma unroll
            for (int rr = 0; rr < 2; rr++) {
                int m = m0 + warp_m + i * 16 + gid + rr * 8;
                float va = acc[i][j][rr * 2 + 0];
                float vb = acc[i][j][rr * 2 + 1];
                if (MODE == 0) {
                    va += bv[nl];  vb += bv[nl + 1];
                    int bb = m >> 10, ss = m & 1023;
                    float* dst = (mat == 0 ? g_q : (mat == 1 ? g_k : g_v));
                    *(float2*)&dst[((bb * NHEADS + h) * SEQ + ss) * DH + nl] = make_float2(va, vb);
                } else if (MODE == 1) {
                    va += B0[n] * inv_h;  vb += B0[n + 1] * inv_h;
                    *(float2*)&out[(m * NNODE + NP + h) * D_MODEL + n] = make_float2(va, vb);
                } else if (MODE == 2) {
                    va = gelu_new(va + B0[n]);  vb = gelu_new(vb + B0[n + 1]);
                    *(float2*)&g_hid[m * DMLP + n] = make_float2(va, vb);
                } else {
                    va += B0[n];  vb += B0[n + 1];
                    *(float2*)&out[(m * NNODE + (NNODE - 1)) * D_MODEL + n] = make_float2(va, vb);
                }
            }
        }
    }
}

// ---------------- flash-attention style causal attention ---------------------------
#define ATTN_SMEM (4 * 64 * 68 * 4)

__global__ __launch_bounds__(256) void k_attn()
{
    extern __shared__ float smem[];
    float (*Qt)[68] = (float(*)[68])(smem);                 // [d][query], pre-scaled
    float (*Kt)[68] = (float(*)[68])(smem + 64 * 68);       // [d][key]
    float (*Vs)[68] = (float(*)[68])(smem + 2 * 64 * 68);   // [key][d]
    float (*Ps)[68] = (float(*)[68])(smem + 3 * 64 * 68);   // [query][key]

    const int qt = blockIdx.x, h = blockIdx.y, b = blockIdx.z;
    const int bh = b * NHEADS + h;
    const int q0 = qt * 64;
    const float* __restrict__ Qb = g_q + (size_t)bh * SEQ * DH;
    const float* __restrict__ Kb = g_k + (size_t)bh * SEQ * DH;
    const float* __restrict__ Vb = g_v + (size_t)bh * SEQ * DH;

    const int tid = threadIdx.x;
    const int ty = tid >> 4, tx = tid & 15;
    const int r0 = ty << 2, c0 = tx << 2;

    {
        int q = tid >> 2, d0 = (tid & 3) << 4;
        const float* src = Qb + (q0 + q) * DH + d0;
#pragma unroll
        for (int j = 0; j < 16; j += 4) {
            float4 v = *(const float4*)(src + j);
            Qt[d0 + j + 0][q] = v.x * 0.125f;
            Qt[d0 + j + 1][q] = v.y * 0.125f;
            Qt[d0 + j + 2][q] = v.z * 0.125f;
            Qt[d0 + j + 3][q] = v.w * 0.125f;
        }
    }

    float m_i[4], l_i[4], o[4][4];
#pragma unroll
    for (int i = 0; i < 4; i++) {
        m_i[i] = -1e30f; l_i[i] = 0.f;
#pragma unroll
        for (int j = 0; j < 4; j++) o[i][j] = 0.f;
    }

    for (int kt = 0; kt <= qt; kt++) {
        const int k0 = kt * 64;
        {
            int kk = tid >> 2, d0 = (tid & 3) << 4;
            const float* ksrc = Kb + (k0 + kk) * DH + d0;
            const float* vsrc = Vb + (k0 + kk) * DH + d0;
#pragma unroll
            for (int j = 0; j < 16; j += 4) {
                float4 kv = *(const float4*)(ksrc + j);
                Kt[d0 + j + 0][kk] = kv.x;
                Kt[d0 + j + 1][kk] = kv.y;
                Kt[d0 + j + 2][kk] = kv.z;
                Kt[d0 + j + 3][kk] = kv.w;
                *(float4*)&Vs[kk][d0 + j] = *(const float4*)(vsrc + j);
            }
        }
        __syncthreads();

        float s[4][4] = {};
#pragma unroll
        for (int d = 0; d < 64; d++) {
            float4 a4 = *(const float4*)&Qt[d][r0];
            float4 b4 = *(const float4*)&Kt[d][c0];
            s[0][0] = fmaf(a4.x, b4.x, s[0][0]); s[0][1] = fmaf(a4.x, b4.y, s[0][1]);
            s[0][2] = fmaf(a4.x, b4.z, s[0][2]); s[0][3] = fmaf(a4.x, b4.w, s[0][3]);
            s[1][0] = fmaf(a4.y, b4.x, s[1][0]); s[1][1] = fmaf(a4.y, b4.y, s[1][1]);
            s[1][2] = fmaf(a4.y, b4.z, s[1][2]); s[1][3] = fmaf(a4.y, b4.w, s[1][3]);
            s[2][0] = fmaf(a4.z, b4.x, s[2][0]); s[2][1] = fmaf(a4.z, b4.y, s[2][1]);
            s[2][2] = fmaf(a4.z, b4.z, s[2][2]); s[2][3] = fmaf(a4.z, b4.w, s[2][3]);
            s[3][0] = fmaf(a4.w, b4.x, s[3][0]); s[3][1] = fmaf(a4.w, b4.y, s[3][1]);
            s[3][2] = fmaf(a4.w, b4.z, s[3][2]); s[3][3] = fmaf(a4.w, b4.w, s[3][3]);
        }

        if (kt == qt) {
#pragma unroll
            for (int i = 0; i < 4; i++)
#pragma unroll
                for (int j = 0; j < 4; j++)
                    if (c0 + j > r0 + i) s[i][j] = -1e30f;
        }

#pragma unroll
        for (int i = 0; i < 4; i++) {
            float mi = fmaxf(fmaxf(s[i][0], s[i][1]), fmaxf(s[i][2], s[i][3]));
#pragma unroll
            for (int off = 1; off < 16; off <<= 1)
                mi = fmaxf(mi, __shfl_xor_sync(0xffffffffu, mi, off));
            float mnew = fmaxf(m_i[i], mi);
            float corr = __expf(m_i[i] - mnew);
            m_i[i] = mnew;
            float p0 = __expf(s[i][0] - mnew);
            float p1 = __expf(s[i][1] - mnew);
            float p2 = __expf(s[i][2] - mnew);
            float p3 = __expf(s[i][3] - mnew);
            float rs = (p0 + p1) + (p2 + p3);
#pragma unroll
            for (int off = 1; off < 16; off <<= 1)
                rs += __shfl_xor_sync(0xffffffffu, rs, off);
            l_i[i] = l_i[i] * corr + rs;
            o[i][0] *= corr; o[i][1] *= corr; o[i][2] *= corr; o[i][3] *= corr;
            *(float4*)&Ps[r0 + i][c0] = make_float4(p0, p1, p2, p3);
        }
        __syncthreads();

#pragma unroll
        for (int kk = 0; kk < 64; kk++) {
            float4 b4 = *(const float4*)&Vs[kk][c0];
            float a0 = Ps[r0 + 0][kk];
            float a1 = Ps[r0 + 1][kk];
            float a2 = Ps[r0 + 2][kk];
            float a3 = Ps[r0 + 3][kk];
            o[0][0] = fmaf(a0, b4.x, o[0][0]); o[0][1] = fmaf(a0, b4.y, o[0][1]);
            o[0][2] = fmaf(a0, b4.z, o[0][2]); o[0][3] = fmaf(a0, b4.w, o[0][3]);
            o[1][0] = fmaf(a1, b4.x, o[1][0]); o[1][1] = fmaf(a1, b4.y, o[1][1]);
            o[1][2] = fmaf(a1, b4.z, o[1][2]); o[1][3] = fmaf(a1, b4.w, o[1][3]);
            o[2][0] = fmaf(a2, b4.x, o[2][0]); o[2][1] = fmaf(a2, b4.y, o[2][1]);
            o[2][2] = fmaf(a2, b4.z, o[2][2]); o[2][3] = fmaf(a2, b4.w, o[2][3]);
            o[3][0] = fmaf(a3, b4.x, o[3][0]); o[3][1] = fmaf(a3, b4.y, o[3][1]);
            o[3][2] = fmaf(a3, b4.z, o[3][2]); o[3][3] = fmaf(a3, b4.w, o[3][3]);
        }
        __syncthreads();
    }

#pragma unroll
    for (int i = 0; i < 4; i++) {
        float inv = 1.f / l_i[i];
        float4 r = make_float4(o[i][0] * inv, o[i][1] * inv, o[i][2] * inv, o[i][3] * inv);
        *(float4*)&g_z[((size_t)bh * SEQ + q0 + r0 + i) * DH + c0] = r;
    }
}

// ---------------- launch -----------------------------------------------------------
extern "C" void kernel_launch(void* const* d_in, const int* in_sizes, int n_in,
                              void* d_out, int out_size)
{
    const float* resid = (const float*)d_in[0];
    const float* mA    = (const float*)d_in[1];
    const float* mM    = (const float*)d_in[2];
    const float* ln1w  = (const float*)d_in[3];
    const float* ln1b  = (const float*)d_in[4];
    const float* ln2w  = (const float*)d_in[5];
    const float* ln2b  = (const float*)d_in[6];
    const float* WQ    = (const float*)d_in[7];
    const float* bQ    = (const float*)d_in[8];
    const float* WK    = (const float*)d_in[9];
    const float* bK    = (const float*)d_in[10];
    const float* WV    = (const float*)d_in[11];
    const float* bV    = (const float*)d_in[12];
    const float* WO    = (const float*)d_in[13];
    const float* bO    = (const float*)d_in[14];
    const float* Win   = (const float*)d_in[15];
    const float* bin   = (const float*)d_in[16];
    const float* Wout  = (const float*)d_in[17];
    const float* bout  = (const float*)d_in[18];
    float* out = (float*)d_out;

    static bool attr_set = false;
    if (!attr_set) {
        cudaFuncSetAttribute(k_attn, cudaFuncAttributeMaxDynamicSharedMemorySize, ATTN_SMEM);
        attr_set = true;
    }

    // 1) fused edge-mask einsums + resid copy
    k_mask_copy<<<(BS * D_MODEL) / 256, 256>>>(resid, mA, mM, out);
    // 2) LN1 (in place)
    k_ln1<<<BS * NHEADS, 256>>>(ln1w, ln1b);
    // 3) Q,K,V projections (36 batched 2048x768x64 GEMMs), tf32 tensor cores
    gemm_tc<0><<<dim3(16, 1, 3 * NHEADS), 256>>>(WQ, WK, WV, bQ, bK, bV, nullptr);
    // 4) causal attention (flash-style, 64-query tiles)
    k_attn<<<dim3(SEQ / 64, NHEADS, NB), 256, ATTN_SMEM>>>();
    // 5) per-head output projection -> output nodes 79..90
    gemm_tc<1><<<dim3(16, 12, NHEADS), 256>>>(WO, nullptr, nullptr, bO, nullptr, nullptr, out);
    // 6) MLP residual mask-sum + LN2
    k_ln2<<<BS, 256>>>(mM, ln2w, ln2b, out);
    // 7) MLP in (gelu)
    gemm_tc<2><<<dim3(16, 48, 1), 256>>>(Win, nullptr, nullptr, bin, nullptr, nullptr, nullptr);
    // 8) MLP out -> output node 91
    gemm_tc<3><<<dim3(16, 12, 1), 256>>>(Wout, nullptr, nullptr, bout, nullptr, nullptr, out);
}